// round 1
// baseline (speedup 1.0000x reference)
#include <cuda_runtime.h>
#include <cuda_bf16.h>
#include <math.h>

// Problem dims (fixed by the reference)
#define S_T 128
#define B_N 512
#define I_N 512
#define H_N 256
#define O_N 256
#define NTOK (S_T * B_N)          // 65536
#define MAX_STEPS 10

// ---- device scratch (allocation-free rule: static __device__ arrays) ----
__device__ float  g_XP  [NTOK * H_N];   // x@W_ih[:, :I]^T + b_ih + b_hh   (64 MB)
__device__ float  g_SACC[NTOK * H_N];   // per-(t,b) s_acc                  (64 MB)
__device__ float  g_P   [NTOK];         // per-(t,b) sum of p_n
__device__ float4 g_W4  [64 * H_N];     // W_hh repacked: g_W4[k4*256+h] = W_hh[h][4k4..4k4+3]

// ---------------------------------------------------------------------------
// Repack W_hh so the recurrent kernel can do coalesced float4 weight loads:
// thread h grabs W_hh[h][4k..4k+3] from g_W4[k4*256 + h].
// ---------------------------------------------------------------------------
__global__ void repack_whh(const float* __restrict__ Whh)
{
    int k4 = blockIdx.x;      // 0..63
    int h  = threadIdx.x;     // 0..255
    const float* row = Whh + (size_t)h * H_N + 4 * k4;
    float4 v;
    v.x = row[0]; v.y = row[1]; v.z = row[2]; v.w = row[3];
    g_W4[k4 * H_N + h] = v;
}

// ---------------------------------------------------------------------------
// Kernel A: XP[n][h] = sum_i x[n][i]*W_ih[h][i] + b_ih[h] + b_hh[h]
//   x:   [NTOK, 512] row-major, W_ih: [256, 513] row-major (col 512 = flag col)
// Tiled fp32 GEMM: 128x128 tile, 256 threads, 8x8 micro-tile (strided).
// ---------------------------------------------------------------------------
__global__ void __launch_bounds__(256) gemm_xp(
    const float* __restrict__ x, const float* __restrict__ Wih,
    const float* __restrict__ b_ih, const float* __restrict__ b_hh)
{
    __shared__ float As[128][17];
    __shared__ float Bs[128][17];

    const int tid = threadIdx.x;
    const int tx = tid & 15, ty = tid >> 4;
    const int m0 = blockIdx.y * 128;
    const int n0 = blockIdx.x * 128;

    const int lr = tid >> 1;          // 0..127
    const int lc = (tid & 1) * 8;     // 0 or 8

    float acc[8][8];
#pragma unroll
    for (int q = 0; q < 8; q++)
#pragma unroll
        for (int p = 0; p < 8; p++) acc[q][p] = 0.f;

    for (int kt = 0; kt < I_N; kt += 16) {
        // A tile (x): float4 loads (aligned: offsets multiple of 8 floats)
        const float* ap = x + (size_t)(m0 + lr) * I_N + kt + lc;
        float4 a0 = *(const float4*)ap;
        float4 a1 = *(const float4*)(ap + 4);
        As[lr][lc + 0] = a0.x; As[lr][lc + 1] = a0.y; As[lr][lc + 2] = a0.z; As[lr][lc + 3] = a0.w;
        As[lr][lc + 4] = a1.x; As[lr][lc + 5] = a1.y; As[lr][lc + 6] = a1.z; As[lr][lc + 7] = a1.w;
        // B tile (W_ih, row stride 513 => odd, scalar loads)
        const float* bp = Wih + (size_t)(n0 + lr) * (I_N + 1) + kt + lc;
#pragma unroll
        for (int j = 0; j < 8; j++) Bs[lr][lc + j] = bp[j];
        __syncthreads();

#pragma unroll
        for (int k = 0; k < 16; k++) {
            float a[8], b[8];
#pragma unroll
            for (int q = 0; q < 8; q++) a[q] = As[ty + 16 * q][k];
#pragma unroll
            for (int p = 0; p < 8; p++) b[p] = Bs[tx + 16 * p][k];
#pragma unroll
            for (int q = 0; q < 8; q++)
#pragma unroll
                for (int p = 0; p < 8; p++) acc[q][p] += a[q] * b[p];
        }
        __syncthreads();
    }

#pragma unroll
    for (int q = 0; q < 8; q++) {
        int m = m0 + ty + 16 * q;
#pragma unroll
        for (int p = 0; p < 8; p++) {
            int h = n0 + tx + 16 * p;
            g_XP[(size_t)m * H_N + h] = acc[q][p] + b_ih[h] + b_hh[h];
        }
    }
}

// ---------------------------------------------------------------------------
// Kernel B: sequential ACT core. 128 CTAs x 256 threads; CTA owns 4 batch rows
// through all 128 timesteps. Thread tid owns hidden unit h=tid for all 4 rows.
// Early-exits the ponder loop when all 4 rows have halted (exact: p_n = 0).
// Writes s_acc -> g_SACC, sum(p) -> g_P, and p_ts/n_ts directly to d_out.
// ---------------------------------------------------------------------------
__global__ void __launch_bounds__(256, 1) act_seq(
    const float* __restrict__ Wih, const float* __restrict__ Whalt,
    const float* __restrict__ bhalt,
    float* __restrict__ pts, float* __restrict__ nts)
{
    const int tid  = threadIdx.x;
    const int b0   = blockIdx.x * 4;
    const int lane = tid & 31, wid = tid >> 5;

    __shared__ float s[4][260];        // current hidden state, row stride 260 (16B aligned)
    __shared__ float red[4][8];        // per-warp halt partials
    __shared__ float sh_p[4], sh_hsum[4], sh_rem[4], sh_nst[4], sh_psum[4];
    __shared__ int   sh_run[4];

    const float fc = Wih[(size_t)tid * (I_N + 1) + I_N];  // flag column W_ih[:,512]
    const float wh = Whalt[tid];
    const float bh = bhalt[0];

#pragma unroll
    for (int r = 0; r < 4; r++) s[r][tid] = 0.f;
    __syncthreads();

    for (int t = 0; t < S_T; t++) {
        float preg[4], sacc[4];
#pragma unroll
        for (int r = 0; r < 4; r++) {
            preg[r] = g_XP[(size_t)(t * B_N + b0 + r) * H_N + tid];
            sacc[r] = 0.f;
        }
        if (tid < 4) {
            sh_hsum[tid] = 0.f; sh_rem[tid] = 0.f; sh_nst[tid] = 0.f;
            sh_psum[tid] = 0.f; sh_run[tid] = 1;
        }
        __syncthreads();

        for (int n = 0; n < MAX_STEPS; n++) {
            float a0 = preg[0], a1 = preg[1], a2 = preg[2], a3 = preg[3];
            if (n == 0) { a0 += fc; a1 += fc; a2 += fc; a3 += fc; }

            const float4* wp = g_W4 + tid;
#pragma unroll 8
            for (int k4 = 0; k4 < 64; k4++) {
                float4 w  = wp[k4 * H_N];
                float4 s0 = *(const float4*)&s[0][k4 * 4];
                float4 s1 = *(const float4*)&s[1][k4 * 4];
                float4 s2 = *(const float4*)&s[2][k4 * 4];
                float4 s3 = *(const float4*)&s[3][k4 * 4];
                a0 += s0.x * w.x + s0.y * w.y + s0.z * w.z + s0.w * w.w;
                a1 += s1.x * w.x + s1.y * w.y + s1.z * w.z + s1.w * w.w;
                a2 += s2.x * w.x + s2.y * w.y + s2.z * w.z + s2.w * w.w;
                a3 += s3.x * w.x + s3.y * w.y + s3.z * w.z + s3.w * w.w;
            }

            float sn0 = tanhf(a0), sn1 = tanhf(a1), sn2 = tanhf(a2), sn3 = tanhf(a3);

            // halt logits: reduce sum_h sn[r][h]*W_halt[h]
            float v0 = sn0 * wh, v1 = sn1 * wh, v2 = sn2 * wh, v3 = sn3 * wh;
#pragma unroll
            for (int off = 16; off; off >>= 1) {
                v0 += __shfl_xor_sync(0xffffffffu, v0, off);
                v1 += __shfl_xor_sync(0xffffffffu, v1, off);
                v2 += __shfl_xor_sync(0xffffffffu, v2, off);
                v3 += __shfl_xor_sync(0xffffffffu, v3, off);
            }
            if (lane == 0) { red[0][wid] = v0; red[1][wid] = v1; red[2][wid] = v2; red[3][wid] = v3; }
            __syncthreads();

            if (tid < 4) {
                int r = tid;
                float hl = bh;
#pragma unroll
                for (int w = 0; w < 8; w++) hl += red[r][w];
                float h = 1.f / (1.f + expf(-hl));
                float p = 0.f;
                if (sh_run[r]) {
                    float hs   = sh_hsum[r];
                    float nsum = hs + h;
                    bool halted = (nsum >= 0.99f);           // 1.0 - EPS
                    p = halted ? (1.f - hs) : h;
                    sh_nst[r] += 1.f;
                    if (halted) { sh_rem[r] = 1.f - hs; sh_run[r] = 0; }
                    sh_hsum[r] = nsum;
                }
                sh_p[r] = p;
                sh_psum[r] += p;
            }
            __syncthreads();

            sacc[0] += sh_p[0] * sn0; s[0][tid] = sn0;
            sacc[1] += sh_p[1] * sn1; s[1][tid] = sn1;
            sacc[2] += sh_p[2] * sn2; s[2][tid] = sn2;
            sacc[3] += sh_p[3] * sn3; s[3][tid] = sn3;
            int any = sh_run[0] | sh_run[1] | sh_run[2] | sh_run[3];
            __syncthreads();
            if (!any) break;
        }

        // per-timestep epilogue
#pragma unroll
        for (int r = 0; r < 4; r++) {
            g_SACC[(size_t)(t * B_N + b0 + r) * H_N + tid] = sacc[r];
            s[r][tid] = sacc[r];                 // s_prev for t+1 is s_acc
        }
        if (tid < 4) {
            int idx = t * B_N + b0 + tid;
            g_P[idx] = sh_psum[tid];
            pts[idx] = sh_nst[tid] + sh_rem[tid];
            nts[idx] = sh_nst[tid];
        }
        __syncthreads();
    }
}

// ---------------------------------------------------------------------------
// Kernel C: y[n][o] = sum_h SACC[n][h]*W_out[o][h] + b_out[o]*P[n]
// Same tiled structure as kernel A (K=256, strides aligned -> float4 loads).
// ---------------------------------------------------------------------------
__global__ void __launch_bounds__(256) gemm_out(
    const float* __restrict__ Wout, const float* __restrict__ b_out,
    float* __restrict__ y)
{
    __shared__ float As[128][17];
    __shared__ float Bs[128][17];

    const int tid = threadIdx.x;
    const int tx = tid & 15, ty = tid >> 4;
    const int m0 = blockIdx.y * 128;
    const int n0 = blockIdx.x * 128;

    const int lr = tid >> 1;
    const int lc = (tid & 1) * 8;

    float acc[8][8];
#pragma unroll
    for (int q = 0; q < 8; q++)
#pragma unroll
        for (int p = 0; p < 8; p++) acc[q][p] = 0.f;

    for (int kt = 0; kt < H_N; kt += 16) {
        const float* ap = g_SACC + (size_t)(m0 + lr) * H_N + kt + lc;
        float4 a0 = *(const float4*)ap;
        float4 a1 = *(const float4*)(ap + 4);
        As[lr][lc + 0] = a0.x; As[lr][lc + 1] = a0.y; As[lr][lc + 2] = a0.z; As[lr][lc + 3] = a0.w;
        As[lr][lc + 4] = a1.x; As[lr][lc + 5] = a1.y; As[lr][lc + 6] = a1.z; As[lr][lc + 7] = a1.w;
        const float* bp = Wout + (size_t)(n0 + lr) * H_N + kt + lc;
        float4 b0v = *(const float4*)bp;
        float4 b1v = *(const float4*)(bp + 4);
        Bs[lr][lc + 0] = b0v.x; Bs[lr][lc + 1] = b0v.y; Bs[lr][lc + 2] = b0v.z; Bs[lr][lc + 3] = b0v.w;
        Bs[lr][lc + 4] = b1v.x; Bs[lr][lc + 5] = b1v.y; Bs[lr][lc + 6] = b1v.z; Bs[lr][lc + 7] = b1v.w;
        __syncthreads();

#pragma unroll
        for (int k = 0; k < 16; k++) {
            float a[8], b[8];
#pragma unroll
            for (int q = 0; q < 8; q++) a[q] = As[ty + 16 * q][k];
#pragma unroll
            for (int p = 0; p < 8; p++) b[p] = Bs[tx + 16 * p][k];
#pragma unroll
            for (int q = 0; q < 8; q++)
#pragma unroll
                for (int p = 0; p < 8; p++) acc[q][p] += a[q] * b[p];
        }
        __syncthreads();
    }

#pragma unroll
    for (int q = 0; q < 8; q++) {
        int m = m0 + ty + 16 * q;
        float pm = g_P[m];
#pragma unroll
        for (int p = 0; p < 8; p++) {
            int o = n0 + tx + 16 * p;
            y[(size_t)m * O_N + o] = acc[q][p] + b_out[o] * pm;
        }
    }
}

// ---------------------------------------------------------------------------
extern "C" void kernel_launch(void* const* d_in, const int* in_sizes, int n_in,
                              void* d_out, int out_size)
{
    const float* x     = (const float*)d_in[0];
    const float* Wih   = (const float*)d_in[1];
    const float* b_ih  = (const float*)d_in[2];
    const float* Whh   = (const float*)d_in[3];
    const float* b_hh  = (const float*)d_in[4];
    const float* Whalt = (const float*)d_in[5];
    const float* bhalt = (const float*)d_in[6];
    const float* Wout  = (const float*)d_in[7];
    const float* b_out = (const float*)d_in[8];

    float* y   = (float*)d_out;                        // [128,512,256]
    float* pts = y + (size_t)NTOK * O_N;               // [128,512]
    float* nts = pts + NTOK;                           // [128,512]

    repack_whh<<<64, 256>>>(Whh);
    gemm_xp<<<dim3(H_N / 128, NTOK / 128), 256>>>(x, Wih, b_ih, b_hh);
    act_seq<<<B_N / 4, 256>>>(Wih, Whalt, bhalt, pts, nts);
    gemm_out<<<dim3(O_N / 128, NTOK / 128), 256>>>(Wout, b_out, y);
}

// round 2
// speedup vs baseline: 1.0726x; 1.0726x over previous
#include <cuda_runtime.h>
#include <cuda_bf16.h>
#include <math.h>

// Problem dims (fixed by the reference)
#define S_T 128
#define B_N 512
#define I_N 512
#define H_N 256
#define O_N 256
#define NTOK (S_T * B_N)          // 65536
#define MAX_STEPS 10

typedef unsigned long long u64;

// packed f32x2 FMA: lanes lo/hi independent IEEE fp32 FMAs (sm_100a)
__device__ __forceinline__ void ffma2(u64 &acc, u64 a, u64 b) {
    asm("fma.rn.f32x2 %0, %1, %2, %0;" : "+l"(acc) : "l"(a), "l"(b));
}
__device__ __forceinline__ u64 pk2(float lo, float hi) {
    u64 r; asm("mov.b64 %0, {%1, %2};" : "=l"(r) : "f"(lo), "f"(hi)); return r;
}
__device__ __forceinline__ float2 upk2(u64 v) {
    float2 f; asm("mov.b64 {%0, %1}, %2;" : "=f"(f.x), "=f"(f.y) : "l"(v)); return f;
}

// ---- device scratch (allocation-free rule: static __device__ arrays) ----
__device__ float  g_XP  [NTOK * H_N];   // x@W_ih[:, :I]^T + b_ih + b_hh   (64 MB)
__device__ float  g_SACC[NTOK * H_N];   // per-(t,b) s_acc                  (64 MB)
__device__ float  g_P   [NTOK];         // per-(t,b) sum of p_n
__device__ float4 g_W4  [64 * H_N];     // W_hh repacked: g_W4[k4*256+h] = W_hh[h][4k4..4k4+3]

// ---------------------------------------------------------------------------
__global__ void repack_whh(const float* __restrict__ Whh)
{
    int k4 = blockIdx.x;      // 0..63
    int h  = threadIdx.x;     // 0..255
    const float* row = Whh + (size_t)h * H_N + 4 * k4;
    float4 v;
    v.x = row[0]; v.y = row[1]; v.z = row[2]; v.w = row[3];
    g_W4[k4 * H_N + h] = v;
}

// ---------------------------------------------------------------------------
// Kernel A: XP[n][h] = sum_i x[n][i]*W_ih[h][i] + b_ih[h] + b_hh[h]
// k-major staging + f32x2 over n-pairs. 128x128 tile, 256 threads,
// micro-tile 8m x 8n (4 n-pairs). 2 CTAs/SM.
// ---------------------------------------------------------------------------
__global__ void __launch_bounds__(256) gemm_xp(
    const float* __restrict__ x, const float* __restrict__ Wih,
    const float* __restrict__ b_ih, const float* __restrict__ b_hh)
{
    __shared__ __align__(16) float As[16][132];   // [k][m]
    __shared__ __align__(16) float Bs[16][132];   // [k][n]

    const int tid = threadIdx.x;
    const int tx = tid & 15, ty = tid >> 4;
    const int m0 = blockIdx.y * 128;
    const int n0 = blockIdx.x * 128;

    const int lr = tid >> 1;          // 0..127 (m or n row being staged)
    const int lc = (tid & 1) * 8;     // k offset 0 or 8

    u64 acc[8][4];
#pragma unroll
    for (int q = 0; q < 8; q++)
#pragma unroll
        for (int p = 0; p < 4; p++) acc[q][p] = 0ull;

    for (int kt = 0; kt < I_N; kt += 16) {
        // stage A (x) transposed: As[k][m]
        const float* ap = x + (size_t)(m0 + lr) * I_N + kt + lc;
        float4 a0 = *(const float4*)ap;
        float4 a1 = *(const float4*)(ap + 4);
        As[lc + 0][lr] = a0.x; As[lc + 1][lr] = a0.y; As[lc + 2][lr] = a0.z; As[lc + 3][lr] = a0.w;
        As[lc + 4][lr] = a1.x; As[lc + 5][lr] = a1.y; As[lc + 6][lr] = a1.z; As[lc + 7][lr] = a1.w;
        // stage B (W_ih, row stride 513 -> scalar) transposed: Bs[k][n]
        const float* bp = Wih + (size_t)(n0 + lr) * (I_N + 1) + kt + lc;
#pragma unroll
        for (int j = 0; j < 8; j++) Bs[lc + j][lr] = bp[j];
        __syncthreads();

#pragma unroll
        for (int k = 0; k < 16; k++) {
            u64 ad[8], bd[4];
#pragma unroll
            for (int q = 0; q < 8; q++) {
                float av = As[k][ty + 16 * q];
                ad[q] = pk2(av, av);
            }
#pragma unroll
            for (int p = 0; p < 4; p++)
                bd[p] = *(const u64*)&Bs[k][tx * 2 + 32 * p];
#pragma unroll
            for (int q = 0; q < 8; q++)
#pragma unroll
                for (int p = 0; p < 4; p++) ffma2(acc[q][p], ad[q], bd[p]);
        }
        __syncthreads();
    }

#pragma unroll
    for (int q = 0; q < 8; q++) {
        int m = m0 + ty + 16 * q;
#pragma unroll
        for (int p = 0; p < 4; p++) {
            int h = n0 + tx * 2 + 32 * p;
            float2 v = upk2(acc[q][p]);
            float2 out;
            out.x = v.x + b_ih[h]     + b_hh[h];
            out.y = v.y + b_ih[h + 1] + b_hh[h + 1];
            *(float2*)&g_XP[(size_t)m * H_N + h] = out;
        }
    }
}

// ---------------------------------------------------------------------------
// Kernel B: sequential ACT core. 128 CTAs x 256 threads; CTA owns 4 batch rows
// through all 128 timesteps. Thread tid owns hidden unit h=tid.
// f32x2 over k-pairs (weights float4 = 2 natural pairs; s float4 = 2 pairs).
// Replicated halting state -> 2 barriers per ponder step.
// ---------------------------------------------------------------------------
__global__ void __launch_bounds__(256, 1) act_seq(
    const float* __restrict__ Wih, const float* __restrict__ Whalt,
    const float* __restrict__ bhalt,
    float* __restrict__ pts, float* __restrict__ nts)
{
    const int tid  = threadIdx.x;
    const int b0   = blockIdx.x * 4;
    const int lane = tid & 31, wid = tid >> 5;

    __shared__ __align__(16) float s[4][264];   // stride 264 floats = 16B-aligned rows
    __shared__ float red[4][8];                 // per-warp halt partials

    const float fc = Wih[(size_t)tid * (I_N + 1) + I_N];  // flag column W_ih[:,512]
    const float wh = Whalt[tid];
    const float bh = bhalt[0];

#pragma unroll
    for (int r = 0; r < 4; r++) s[r][tid] = 0.f;
    __syncthreads();

    for (int t = 0; t < S_T; t++) {
        float pre[4], sacc[4];
#pragma unroll
        for (int r = 0; r < 4; r++) {
            pre[r]  = g_XP[(size_t)(t * B_N + b0 + r) * H_N + tid];
            sacc[r] = 0.f;
        }
        // replicated per-row halting state (identical in every thread)
        float hsum[4] = {0.f, 0.f, 0.f, 0.f};
        float rem [4] = {0.f, 0.f, 0.f, 0.f};
        float nst [4] = {0.f, 0.f, 0.f, 0.f};
        float psum[4] = {0.f, 0.f, 0.f, 0.f};
        bool  run [4] = {true, true, true, true};

        for (int n = 0; n < MAX_STEPS; n++) {
            u64 aA[4], aB[4];
            float base = (n == 0) ? fc : 0.f;
#pragma unroll
            for (int r = 0; r < 4; r++) {
                aA[r] = pk2(pre[r] + base, 0.f);
                aB[r] = 0ull;
            }

            const ulonglong2* wp = reinterpret_cast<const ulonglong2*>(g_W4) + tid;
#pragma unroll 8
            for (int k4 = 0; k4 < 64; k4++) {
                ulonglong2 w  = wp[k4 * H_N];                                   // (w[k],w[k+1]),(w[k+2],w[k+3])
                ulonglong2 s0 = *(const ulonglong2*)&s[0][k4 * 4];
                ulonglong2 s1 = *(const ulonglong2*)&s[1][k4 * 4];
                ulonglong2 s2 = *(const ulonglong2*)&s[2][k4 * 4];
                ulonglong2 s3 = *(const ulonglong2*)&s[3][k4 * 4];
                ffma2(aA[0], s0.x, w.x); ffma2(aB[0], s0.y, w.y);
                ffma2(aA[1], s1.x, w.x); ffma2(aB[1], s1.y, w.y);
                ffma2(aA[2], s2.x, w.x); ffma2(aB[2], s2.y, w.y);
                ffma2(aA[3], s3.x, w.x); ffma2(aB[3], s3.y, w.y);
            }

            float sn[4];
#pragma unroll
            for (int r = 0; r < 4; r++) {
                float2 u = upk2(aA[r]), v = upk2(aB[r]);
                sn[r] = tanhf((u.x + u.y) + (v.x + v.y));
            }

            // halt logits: cross-thread reduce of sn[r]*W_halt[h]
            float v0 = sn[0] * wh, v1 = sn[1] * wh, v2 = sn[2] * wh, v3 = sn[3] * wh;
#pragma unroll
            for (int off = 16; off; off >>= 1) {
                v0 += __shfl_xor_sync(0xffffffffu, v0, off);
                v1 += __shfl_xor_sync(0xffffffffu, v1, off);
                v2 += __shfl_xor_sync(0xffffffffu, v2, off);
                v3 += __shfl_xor_sync(0xffffffffu, v3, off);
            }
            if (lane == 0) { red[0][wid] = v0; red[1][wid] = v1; red[2][wid] = v2; red[3][wid] = v3; }
            __syncthreads();   // red visible; everyone done reading old s

            bool anyrun = false;
#pragma unroll
            for (int r = 0; r < 4; r++) {
                float hl = bh;
#pragma unroll
                for (int w = 0; w < 8; w++) hl += red[r][w];
                float h = 1.f / (1.f + expf(-hl));
                float p = 0.f;
                if (run[r]) {
                    float ns = hsum[r] + h;
                    bool halted = (ns >= 0.99f);            // 1.0 - EPS
                    p = halted ? (1.f - hsum[r]) : h;
                    nst[r] += 1.f;
                    if (halted) { rem[r] = 1.f - hsum[r]; run[r] = false; }
                    hsum[r] = ns;
                }
                psum[r] += p;
                sacc[r] += p * sn[r];
                s[r][tid] = sn[r];
                anyrun |= run[r];
            }
            __syncthreads();   // new s visible
            if (!anyrun) break;
        }

        // per-timestep epilogue
#pragma unroll
        for (int r = 0; r < 4; r++) {
            g_SACC[(size_t)(t * B_N + b0 + r) * H_N + tid] = sacc[r];
            s[r][tid] = sacc[r];                 // s_prev for t+1 is s_acc
        }
        if (tid < 4) {
            int idx = t * B_N + b0 + tid;
            float ps = (tid == 0) ? psum[0] : (tid == 1) ? psum[1] : (tid == 2) ? psum[2] : psum[3];
            float nn = (tid == 0) ? nst [0] : (tid == 1) ? nst [1] : (tid == 2) ? nst [2] : nst [3];
            float rr = (tid == 0) ? rem [0] : (tid == 1) ? rem [1] : (tid == 2) ? rem [2] : rem [3];
            g_P[idx] = ps;
            pts[idx] = nn + rr;
            nts[idx] = nn;
        }
        __syncthreads();
    }
}

// ---------------------------------------------------------------------------
// Kernel C: y[n][o] = sum_h SACC[n][h]*W_out[o][h] + b_out[o]*P[n]
// Same f32x2 k-major structure as kernel A (K=256, aligned float4 staging).
// ---------------------------------------------------------------------------
__global__ void __launch_bounds__(256) gemm_out(
    const float* __restrict__ Wout, const float* __restrict__ b_out,
    float* __restrict__ y)
{
    __shared__ __align__(16) float As[16][132];
    __shared__ __align__(16) float Bs[16][132];

    const int tid = threadIdx.x;
    const int tx = tid & 15, ty = tid >> 4;
    const int m0 = blockIdx.y * 128;
    const int n0 = blockIdx.x * 128;

    const int lr = tid >> 1;
    const int lc = (tid & 1) * 8;

    u64 acc[8][4];
#pragma unroll
    for (int q = 0; q < 8; q++)
#pragma unroll
        for (int p = 0; p < 4; p++) acc[q][p] = 0ull;

    for (int kt = 0; kt < H_N; kt += 16) {
        const float* ap = g_SACC + (size_t)(m0 + lr) * H_N + kt + lc;
        float4 a0 = *(const float4*)ap;
        float4 a1 = *(const float4*)(ap + 4);
        As[lc + 0][lr] = a0.x; As[lc + 1][lr] = a0.y; As[lc + 2][lr] = a0.z; As[lc + 3][lr] = a0.w;
        As[lc + 4][lr] = a1.x; As[lc + 5][lr] = a1.y; As[lc + 6][lr] = a1.z; As[lc + 7][lr] = a1.w;
        const float* bp = Wout + (size_t)(n0 + lr) * H_N + kt + lc;
        float4 b0v = *(const float4*)bp;
        float4 b1v = *(const float4*)(bp + 4);
        Bs[lc + 0][lr] = b0v.x; Bs[lc + 1][lr] = b0v.y; Bs[lc + 2][lr] = b0v.z; Bs[lc + 3][lr] = b0v.w;
        Bs[lc + 4][lr] = b1v.x; Bs[lc + 5][lr] = b1v.y; Bs[lc + 6][lr] = b1v.z; Bs[lc + 7][lr] = b1v.w;
        __syncthreads();

#pragma unroll
        for (int k = 0; k < 16; k++) {
            u64 ad[8], bd[4];
#pragma unroll
            for (int q = 0; q < 8; q++) {
                float av = As[k][ty + 16 * q];
                ad[q] = pk2(av, av);
            }
#pragma unroll
            for (int p = 0; p < 4; p++)
                bd[p] = *(const u64*)&Bs[k][tx * 2 + 32 * p];
#pragma unroll
            for (int q = 0; q < 8; q++)
#pragma unroll
                for (int p = 0; p < 4; p++) ffma2(acc[q][p], ad[q], bd[p]);
        }
        __syncthreads();
    }

#pragma unroll
    for (int q = 0; q < 8; q++) {
        int m = m0 + ty + 16 * q;
        float pm = g_P[m];
#pragma unroll
        for (int p = 0; p < 4; p++) {
            int o = n0 + tx * 2 + 32 * p;
            float2 v = upk2(acc[q][p]);
            float2 out;
            out.x = v.x + b_out[o]     * pm;
            out.y = v.y + b_out[o + 1] * pm;
            *(float2*)&y[(size_t)m * O_N + o] = out;
        }
    }
}

// ---------------------------------------------------------------------------
extern "C" void kernel_launch(void* const* d_in, const int* in_sizes, int n_in,
                              void* d_out, int out_size)
{
    const float* x     = (const float*)d_in[0];
    const float* Wih   = (const float*)d_in[1];
    const float* b_ih  = (const float*)d_in[2];
    const float* Whh   = (const float*)d_in[3];
    const float* b_hh  = (const float*)d_in[4];
    const float* Whalt = (const float*)d_in[5];
    const float* bhalt = (const float*)d_in[6];
    const float* Wout  = (const float*)d_in[7];
    const float* b_out = (const float*)d_in[8];

    float* y   = (float*)d_out;                        // [128,512,256]
    float* pts = y + (size_t)NTOK * O_N;               // [128,512]
    float* nts = pts + NTOK;                           // [128,512]

    repack_whh<<<64, 256>>>(Whh);
    gemm_xp<<<dim3(H_N / 128, NTOK / 128), 256>>>(x, Wih, b_ih, b_hh);
    act_seq<<<B_N / 4, 256>>>(Wih, Whalt, bhalt, pts, nts);
    gemm_out<<<dim3(O_N / 128, NTOK / 128), 256>>>(Wout, b_out, y);
}